// round 2
// baseline (speedup 1.0000x reference)
#include <cuda_runtime.h>
#include <cstdint>

// ----------------------------------------------------------------------------
// Problem dims (fixed by dataset)
// ----------------------------------------------------------------------------
#define MDIM 8192   // B*S rows
#define NDIM 4096   // reduction dim
#define KDIM 4096   // output features
#define NGROUPS 32

// GEMM tiling
#define TILE_M  128          // CTA rows
#define TILE_KO 256          // CTA output features
#define CHUNK   32           // reduction elems per stage
#define STAGES  3
#define NCHUNK  (NDIM / CHUNK)   // 128

// Smem strides (floats). 36 = 32 + 4 pad -> fragment LDS addresses are
// (g*36 + c) mod 32 = (4g + c) mod 32, unique across the warp: conflict-free.
#define SA_STRIDE 36
#define SB_STRIDE 36
#define SA_FLOATS (TILE_M  * SA_STRIDE)        // 4608
#define SB_FLOATS (TILE_KO * SB_STRIDE)        // 9216
#define STAGE_FLOATS (SA_FLOATS + SB_FLOATS)   // 13824
#define SMEM_BYTES (STAGES * STAGE_FLOATS * 4) // 165888

// ----------------------------------------------------------------------------
// Device scratch (allocation-free rule: __device__ global)
// ----------------------------------------------------------------------------
__device__ float g_Wdeq[(size_t)KDIM * NDIM];   // 64 MB dequantized W (tf32-RN)

// ----------------------------------------------------------------------------
// Helpers
// ----------------------------------------------------------------------------
__device__ __forceinline__ uint32_t smem_u32(const void* p) {
    uint32_t a;
    asm("{ .reg .u64 t; cvta.to.shared.u64 t, %1; cvt.u32.u64 %0, t; }"
        : "=r"(a) : "l"(p));
    return a;
}

// Round fp32 to nearest tf32-representable value, return raw bits.
__device__ __forceinline__ uint32_t rna_tf32_bits(float x) {
    uint32_t u;
    asm("cvt.rna.tf32.f32 %0, %1;" : "=r"(u) : "f"(x));
    return u;
}
__device__ __forceinline__ float rna_tf32(float x) {
    return __uint_as_float(rna_tf32_bits(x));
}

__device__ __forceinline__ void cp_async16(uint32_t sdst, const void* gsrc) {
    asm volatile("cp.async.cg.shared.global [%0], [%1], 16;"
                 :: "r"(sdst), "l"(gsrc) : "memory");
}

__device__ __forceinline__ void mma_tf32(float* d, const uint32_t* a,
                                         const uint32_t* b) {
    asm volatile(
        "mma.sync.aligned.m16n8k8.row.col.f32.tf32.tf32.f32 "
        "{%0,%1,%2,%3}, {%4,%5,%6,%7}, {%8,%9}, {%0,%1,%2,%3};"
        : "+f"(d[0]), "+f"(d[1]), "+f"(d[2]), "+f"(d[3])
        : "r"(a[0]), "r"(a[1]), "r"(a[2]), "r"(a[3]), "r"(b[0]), "r"(b[1]));
}

// ----------------------------------------------------------------------------
// Kernel 1: dequantize W (scales/zeros/mu2/mu1 fused), rounded to tf32-RN
// ----------------------------------------------------------------------------
__global__ void dequant_kernel(const int* __restrict__ Wq,
                               const float* __restrict__ scales,
                               const float* __restrict__ zeros,
                               const float* __restrict__ mu1,
                               const float* __restrict__ mu2) {
    int k = blockIdx.x;
    float m2 = mu2[k];
    const int4* wrow = reinterpret_cast<const int4*>(Wq + (size_t)k * NDIM);
    float4* drow = reinterpret_cast<float4*>(g_Wdeq + (size_t)k * NDIM);
    for (int n4 = threadIdx.x; n4 < NDIM / 4; n4 += blockDim.x) {
        int n = n4 * 4;
        int g = n >> 7;   // group = n / 128
        float s = scales[k * NGROUPS + g] * m2;
        float z = zeros[k * NGROUPS + g];
        int4 q = wrow[n4];
        float4 o;
        o.x = rna_tf32(((float)q.x - z) * s * mu1[n + 0]);
        o.y = rna_tf32(((float)q.y - z) * s * mu1[n + 1]);
        o.z = rna_tf32(((float)q.z - z) * s * mu1[n + 2]);
        o.w = rna_tf32(((float)q.w - z) * s * mu1[n + 3]);
        drow[n4] = o;
    }
}

// ----------------------------------------------------------------------------
// Kernel 2: tf32 mma.sync GEMM.  out[m,k] = sum_n X[m,n] * Wdeq[k,n] + bias[k]
// CTA 128x256, 8 warps (2 M x 4 Kout), warp tile 64x64, 3-stage cp.async.
// ----------------------------------------------------------------------------
__global__ void __launch_bounds__(256, 1)
gemm_kernel(const float* __restrict__ x,
            const float* __restrict__ bias,
            float* __restrict__ out) {
    extern __shared__ float smem[];

    const int tid = threadIdx.x;
    const int wid = tid >> 5;
    const int lane = tid & 31;
    const int g = lane >> 2;      // group-of-4 id (0..7)
    const int c = lane & 3;       // thread-in-group (0..3)
    const int wm = wid & 1;       // warp row  (0..1)
    const int wn = wid >> 1;      // warp col  (0..3)

    const int k0 = blockIdx.x * TILE_KO;
    const int m0 = blockIdx.y * TILE_M;

    float acc[4][8][4];
    #pragma unroll
    for (int mi = 0; mi < 4; mi++)
        #pragma unroll
        for (int ni = 0; ni < 8; ni++)
            #pragma unroll
            for (int r = 0; r < 4; r++) acc[mi][ni][r] = 0.f;

    // ---- async copy of one stage ----
    auto issue = [&](int chunk, int buf) {
        const int n0 = chunk * CHUNK;
        float* sA = smem + buf * STAGE_FLOATS;
        float* sB = sA + SA_FLOATS;
        #pragma unroll
        for (int i = 0; i < 4; i++) {            // A: 128 rows x 32 floats
            int id = tid + i * 256;
            int row = id >> 3, cc = id & 7;
            cp_async16(smem_u32(sA + row * SA_STRIDE + cc * 4),
                       x + (size_t)(m0 + row) * NDIM + n0 + cc * 4);
        }
        #pragma unroll
        for (int i = 0; i < 8; i++) {            // B: 256 rows x 32 floats
            int id = tid + i * 256;
            int row = id >> 3, cc = id & 7;
            cp_async16(smem_u32(sB + row * SB_STRIDE + cc * 4),
                       g_Wdeq + (size_t)(k0 + row) * NDIM + n0 + cc * 4);
        }
        asm volatile("cp.async.commit_group;" ::: "memory");
    };

    // ---- compute one stage (k-chunk of 32 = 4 MMA k-steps) ----
    auto compute = [&](int buf) {
        const float* sA = smem + buf * STAGE_FLOATS + (wm * 64) * SA_STRIDE;
        const float* sB = smem + buf * STAGE_FLOATS + SA_FLOATS
                               + (wn * 64) * SB_STRIDE;
        #pragma unroll
        for (int ks = 0; ks < 4; ks++) {
            const int col = ks * 8 + c;
            uint32_t a[4][4], b[8][2];
            #pragma unroll
            for (int mi = 0; mi < 4; mi++) {
                const float* ap = sA + (mi * 16 + g) * SA_STRIDE + col;
                a[mi][0] = rna_tf32_bits(ap[0]);
                a[mi][1] = rna_tf32_bits(ap[8 * SA_STRIDE]);
                a[mi][2] = rna_tf32_bits(ap[4]);
                a[mi][3] = rna_tf32_bits(ap[8 * SA_STRIDE + 4]);
            }
            #pragma unroll
            for (int ni = 0; ni < 8; ni++) {
                const float* bp = sB + (ni * 8 + g) * SB_STRIDE + col;
                b[ni][0] = __float_as_uint(bp[0]);   // Wdeq pre-rounded
                b[ni][1] = __float_as_uint(bp[4]);
            }
            #pragma unroll
            for (int mi = 0; mi < 4; mi++)
                #pragma unroll
                for (int ni = 0; ni < 8; ni++)
                    mma_tf32(acc[mi][ni], a[mi], b[ni]);
        }
    };

    // ---- pipeline ----
    issue(0, 0);
    issue(1, 1);
    for (int i = 0; i < NCHUNK; i++) {
        if (i < NCHUNK - 1)
            asm volatile("cp.async.wait_group 1;" ::: "memory");
        else
            asm volatile("cp.async.wait_group 0;" ::: "memory");
        __syncthreads();
        if (i + 2 < NCHUNK) issue(i + 2, (i + 2) % STAGES);
        compute(i % STAGES);
        __syncthreads();
    }

    // ---- epilogue: bias + store ----
    #pragma unroll
    for (int ni = 0; ni < 8; ni++) {
        const int col = k0 + wn * 64 + ni * 8 + 2 * c;
        const float2 bv = *reinterpret_cast<const float2*>(bias + col);
        #pragma unroll
        for (int mi = 0; mi < 4; mi++) {
            const int row0 = m0 + wm * 64 + mi * 16 + g;
            float2 v0, v1;
            v0.x = acc[mi][ni][0] + bv.x;  v0.y = acc[mi][ni][1] + bv.y;
            v1.x = acc[mi][ni][2] + bv.x;  v1.y = acc[mi][ni][3] + bv.y;
            *reinterpret_cast<float2*>(out + (size_t)row0 * KDIM + col) = v0;
            *reinterpret_cast<float2*>(out + (size_t)(row0 + 8) * KDIM + col) = v1;
        }
    }
}

// ----------------------------------------------------------------------------
// Host launch
// ----------------------------------------------------------------------------
extern "C" void kernel_launch(void* const* d_in, const int* in_sizes, int n_in,
                              void* d_out, int out_size) {
    const float* x      = (const float*)d_in[0];
    const int*   Wq     = (const int*)d_in[1];
    const float* scales = (const float*)d_in[2];
    const float* zeros  = (const float*)d_in[3];
    const float* mu1    = (const float*)d_in[4];
    const float* mu2    = (const float*)d_in[5];
    const float* bias   = (const float*)d_in[6];
    float* out = (float*)d_out;

    dequant_kernel<<<KDIM, 256>>>(Wq, scales, zeros, mu1, mu2);

    static bool attr_set = false;
    if (!attr_set) {
        cudaFuncSetAttribute(gemm_kernel,
                             cudaFuncAttributeMaxDynamicSharedMemorySize,
                             SMEM_BYTES);
        attr_set = true;
    }
    dim3 grid(KDIM / TILE_KO, MDIM / TILE_M);   // (16, 64)
    gemm_kernel<<<grid, 256, SMEM_BYTES>>>(x, bias, out);
}